// round 10
// baseline (speedup 1.0000x reference)
#include <cuda_runtime.h>

// Decoder_predict: batched greedy goals-NMS.  B=256, N=4096, T=30, K=6.
// scores = class * centerness, thr^2 = 4.0.
//
// V10: byte diet (stream only cls+cent = 8 MB) + restored memory-level
// parallelism: 256 thr/CTA, 16 contiguous candidates per thread = 8
// independent float4 loads in flight per thread (measured: 8 wide
// loads/thread sustains ~1.33 TB/s in this kernel's regime, vs ~1.0 TB/s
// at 4 loads/thread).
//  - Phase 1 (8 warps): per-warp top-6 by u32 score bits; ballot lowest-lane
//    + lowest-slot = exact lowest-original-index tie-break; winning lane
//    immediately gathers that survivor's float2 coord (overlapped with the
//    remaining reduction rounds). 48 survivors -> smem.
//  - Phase 2 (warp 0): 6 greedy NMS rounds over 48 survivors (2/lane), u32
//    butterflies only; lane 0 writes probs/goals straight to global and
//    releases per-round flags.
//  - Phase 3 (warps 1..6): spin on their round's flag, then gather that
//    trajectory row (15 x float4). Single __syncthreads in the kernel.

#define NMS_B 256
#define NMS_N 4096
#define NMS_T 30
#define NMS_K 6
#define NMS_THR2 4.0f
#define THREADS 256
#define WARPS 8
#define SURV (WARPS * NMS_K)   // 48

__global__ __launch_bounds__(THREADS)
void nms_goals_kernel(const float* __restrict__ coord,   // [B,1,N,2]
                      const float* __restrict__ cls,     // [B,1,N]
                      const float* __restrict__ traj,    // [B,1,N,T,2]
                      const float* __restrict__ cent,    // [B,1,N]
                      float* __restrict__ out)
{
    const int b    = blockIdx.x;
    const int tid  = threadIdx.x;
    const int wid  = tid >> 5;
    const int lane = tid & 31;

    __shared__ unsigned skey[SURV + 16];   // score bits, 0 = empty (pad to 64)
    __shared__ int      sidx[SURV];
    __shared__ float2   scoord[SURV];
    __shared__ int      sel_i[NMS_K];
    __shared__ volatile int flags[NMS_K];

    if (tid < NMS_K) flags[tid] = 0;
    if (tid < 16)    skey[SURV + tid] = 0u;   // empty tail slots for phase 2

    // ---- Phase 1: scores only; 16 contiguous candidates per thread. ----
    {
        const float4* s4   = (const float4*)(cls  + (size_t)b * NMS_N);
        const float4* e4   = (const float4*)(cent + (size_t)b * NMS_N);
        const float2* cptr = (const float2*)(coord + (size_t)b * NMS_N * 2);

        // 8 independent wide loads, all issued before any use.
        float4 sv[4], ev[4];
#pragma unroll
        for (int k = 0; k < 4; k++) sv[k] = s4[4 * tid + k];
#pragma unroll
        for (int k = 0; k < 4; k++) ev[k] = e4[4 * tid + k];

        unsigned sc[16];
#pragma unroll
        for (int k = 0; k < 4; k++) {
            sc[4*k + 0] = __float_as_uint(sv[k].x * ev[k].x);
            sc[4*k + 1] = __float_as_uint(sv[k].y * ev[k].y);
            sc[4*k + 2] = __float_as_uint(sv[k].z * ev[k].z);
            sc[4*k + 3] = __float_as_uint(sv[k].w * ev[k].w);
        }

        unsigned tmax = sc[0];
#pragma unroll
        for (int j = 1; j < 16; j++) tmax = max(tmax, sc[j]);

#pragma unroll
        for (int r = 0; r < NMS_K; r++) {
            unsigned m = tmax;
#pragma unroll
            for (int off = 16; off > 0; off >>= 1)
                m = max(m, __shfl_xor_sync(0xFFFFFFFFu, m, off));

            if (m == 0u) {
                if (lane == 0) skey[wid * NMS_K + r] = 0u;   // empty slot
            } else {
                const bool mine = (tmax == m);
                const unsigned bal = __ballot_sync(0xFFFFFFFFu, mine);
                const int wl = __ffs(bal) - 1;    // lowest lane = lowest idx
                if (lane == wl) {
                    int jm = 15;
#pragma unroll
                    for (int j = 15; j >= 0; j--)
                        if (sc[j] == m) jm = j;   // lowest slot = lowest idx
                    const int idx = 16 * tid + jm;
                    const int s   = wid * NMS_K + r;
                    skey[s]   = m;
                    sidx[s]   = idx;
                    scoord[s] = cptr[idx];        // overlapped coord gather
#pragma unroll
                    for (int j = 0; j < 16; j++) if (sc[j] == m) sc[j] = 0u;
                    tmax = sc[0];
#pragma unroll
                    for (int j = 1; j < 16; j++) tmax = max(tmax, sc[j]);
                }
            }
        }
    }
    __syncthreads();    // the only block barrier

    // ---- Phase 2: warp 0 greedy NMS over 48 survivors (2/lane, u32). ----
    if (wid == 0) {
        unsigned vp[2];
        float vx[2], vy[2];
#pragma unroll
        for (int h = 0; h < 2; h++) {
            const int s = lane + 32 * h;       // slots 48..63 are empty (0)
            vp[h] = skey[s];
            if (s < SURV) {
                const float2 c = scoord[s];
                vx[h] = c.x;  vy[h] = c.y;
            } else { vx[h] = 0.f; vy[h] = 0.f; }
        }

        float* out_prob = out + (size_t)NMS_B * NMS_K * NMS_T * 2;
        float* out_goal = out_prob + (size_t)NMS_B * NMS_K;
        float  s0 = 0.0f;   // round-0 score (fallback semantics)

#pragma unroll
        for (int r = 0; r < NMS_K; r++) {
            unsigned m = max(vp[0], vp[1]);
#pragma unroll
            for (int off = 16; off > 0; off >>= 1)
                m = max(m, __shfl_xor_sync(0xFFFFFFFFu, m, off));

            if (m == 0u) {
                // Fallback: reference keeps sel_idx = 0 -> round-0 point's
                // score/traj, goal (0,0).
                if (lane == 0) {
                    sel_i[r] = -1;
                    out_prob[(size_t)b * NMS_K + r]           = s0;
                    out_goal[((size_t)b * NMS_K + r) * 2 + 0] = 0.0f;
                    out_goal[((size_t)b * NMS_K + r) * 2 + 1] = 0.0f;
                    __threadfence_block();
                    flags[r] = 1;
                }
            } else {
                // Lowest-slot tie-break: prefer h=0 block, lowest lane in it.
                const unsigned b0 = __ballot_sync(0xFFFFFFFFu, vp[0] == m);
                const unsigned b1 = __ballot_sync(0xFFFFFFFFu, vp[1] == m);
                int hsel, wl;
                if (b0) { hsel = 0; wl = __ffs(b0) - 1; }
                else    { hsel = 1; wl = __ffs(b1) - 1; }

                const float fx = (hsel == 0) ? vx[0] : vx[1];
                const float fy = (hsel == 0) ? vy[0] : vy[1];
                const float px = __shfl_sync(0xFFFFFFFFu, fx, wl);
                const float py = __shfl_sync(0xFFFFFFFFu, fy, wl);
                if (r == 0) s0 = __uint_as_float(m);

                if (lane == 0) {
                    sel_i[r] = sidx[wl + 32 * hsel];
                    out_prob[(size_t)b * NMS_K + r]           = __uint_as_float(m);
                    out_goal[((size_t)b * NMS_K + r) * 2 + 0] = px;
                    out_goal[((size_t)b * NMS_K + r) * 2 + 1] = py;
                    __threadfence_block();
                    flags[r] = 1;     // release this round's selection
                }
                // Suppress survivors within thr (incl. the winner itself).
#pragma unroll
                for (int h = 0; h < 2; h++) {
                    const float dx = vx[h] - px;
                    const float dy = vy[h] - py;
                    if (dx * dx + dy * dy < NMS_THR2) vp[h] = 0u;
                }
            }
            __syncwarp();
        }
    }
    // ---- Phase 3: traj gathers start as soon as their round resolves. ----
    else if (wid <= NMS_K) {            // warps 1..6 -> traj row (wid-1)
        const int r = wid - 1;
        while (flags[r] == 0) { }
        __threadfence_block();
        const int sr = sel_i[r];
        int src = (sr >= 0) ? sr : sel_i[0];
        if (src < 0) src = 0;           // unreachable; memory safety only
        if (lane < 15) {
            ((float4*)out)[((size_t)b * NMS_K + r) * 15 + lane] =
                ((const float4*)traj)[((size_t)b * NMS_N + src) * 15 + lane];
        }
    }
    // warp 7: done after phase 1.
}

extern "C" void kernel_launch(void* const* d_in, const int* in_sizes, int n_in,
                              void* d_out, int out_size) {
    const float* coord = (const float*)d_in[0];  // outputs_coord     [B,1,N,2]
    const float* cls   = (const float*)d_in[1];  // outputs_class     [B,1,N]
    const float* traj  = (const float*)d_in[2];  // outputs_traj      [B,1,N,T,2]
    const float* cent  = (const float*)d_in[3];  // outputs_centerness[B,1,N]
    float* out = (float*)d_out;

    nms_goals_kernel<<<NMS_B, THREADS>>>(coord, cls, traj, cent, out);
}

// round 11
// speedup vs baseline: 1.0269x; 1.0269x over previous
#include <cuda_runtime.h>

// Decoder_predict: batched greedy goals-NMS.  B=256, N=4096, T=30, K=6.
// scores = class * centerness, thr^2 = 4.0.
//
// V11: WAVE QUANTIZATION FIX. All previous variants used grid=256 on 148 SMs
// (1.73 waves) and all measured ~= 2 x per-CTA time. This version fuses TWO
// batches per CTA: grid = 128 (single wave), 512 threads; warps 0-7 run
// batch 2*blk, warps 8-15 run batch 2*blk+1 as two independent pipelines.
//  - Phase 1 (per half, 8 warps): stream only cls+cent; 16 contiguous
//    candidates/thread (4x float4 cls + 4x float4 cent); per-warp top-6 by
//    u32 score bits; ballot lowest-lane + lowest-slot = exact lowest-index
//    tie-break; winning lane gathers that survivor's float2 coord
//    immediately (overlapped). 48 survivors per half -> smem.
//  - Phase 2: warp 0 (half 0) and warp 8 (half 1) run the 6 greedy NMS
//    rounds over their 48 survivors (2/lane, u32 butterflies); lane 0
//    writes probs/goals to global and releases per-round flags.
//  - Phase 3: warps 1..6 / 9..14 gather their trajectory row (15 x float4)
//    as soon as their round's flag is set. One __syncthreads total.

#define NMS_B 256
#define NMS_N 4096
#define NMS_T 30
#define NMS_K 6
#define NMS_THR2 4.0f
#define THREADS 512
#define HWARPS 8                 // warps per half (per batch)
#define SURV (HWARPS * NMS_K)    // 48 per half

__global__ __launch_bounds__(THREADS)
void nms_goals_kernel(const float* __restrict__ coord,   // [B,1,N,2]
                      const float* __restrict__ cls,     // [B,1,N]
                      const float* __restrict__ traj,    // [B,1,N,T,2]
                      const float* __restrict__ cent,    // [B,1,N]
                      float* __restrict__ out)
{
    const int tid  = threadIdx.x;
    const int wid  = tid >> 5;
    const int lane = tid & 31;
    const int h    = wid >> 3;                  // half: 0 or 1
    const int b    = 2 * blockIdx.x + h;        // this half's batch
    const int hw   = wid & 7;                   // warp id within half
    const int ht   = tid & 255;                 // thread id within half

    __shared__ unsigned skey[2][SURV + 16];     // score bits, 0 = empty
    __shared__ int      sidx[2][SURV];
    __shared__ float2   scoord[2][SURV];
    __shared__ int      sel_i[2][NMS_K];
    __shared__ volatile int flags[2][NMS_K];

    if (tid < 2 * NMS_K) flags[tid / NMS_K][tid % NMS_K] = 0;
    if (tid < 32)        skey[tid >> 4][SURV + (tid & 15)] = 0u;

    // ---- Phase 1: scores only; 16 contiguous candidates per thread. ----
    {
        const float4* s4   = (const float4*)(cls  + (size_t)b * NMS_N);
        const float4* e4   = (const float4*)(cent + (size_t)b * NMS_N);
        const float2* cptr = (const float2*)(coord + (size_t)b * NMS_N * 2);

        float4 sv[4], ev[4];
#pragma unroll
        for (int k = 0; k < 4; k++) sv[k] = s4[4 * ht + k];
#pragma unroll
        for (int k = 0; k < 4; k++) ev[k] = e4[4 * ht + k];

        unsigned sc[16];
#pragma unroll
        for (int k = 0; k < 4; k++) {
            sc[4*k + 0] = __float_as_uint(sv[k].x * ev[k].x);
            sc[4*k + 1] = __float_as_uint(sv[k].y * ev[k].y);
            sc[4*k + 2] = __float_as_uint(sv[k].z * ev[k].z);
            sc[4*k + 3] = __float_as_uint(sv[k].w * ev[k].w);
        }

        unsigned tmax = sc[0];
#pragma unroll
        for (int j = 1; j < 16; j++) tmax = max(tmax, sc[j]);

#pragma unroll
        for (int r = 0; r < NMS_K; r++) {
            unsigned m = tmax;
#pragma unroll
            for (int off = 16; off > 0; off >>= 1)
                m = max(m, __shfl_xor_sync(0xFFFFFFFFu, m, off));

            if (m == 0u) {
                if (lane == 0) skey[h][hw * NMS_K + r] = 0u;   // empty slot
            } else {
                const bool mine = (tmax == m);
                const unsigned bal = __ballot_sync(0xFFFFFFFFu, mine);
                const int wl = __ffs(bal) - 1;    // lowest lane = lowest idx
                if (lane == wl) {
                    int jm = 15;
#pragma unroll
                    for (int j = 15; j >= 0; j--)
                        if (sc[j] == m) jm = j;   // lowest slot = lowest idx
                    const int idx = 16 * ht + jm;
                    const int s   = hw * NMS_K + r;
                    skey[h][s]   = m;
                    sidx[h][s]   = idx;
                    scoord[h][s] = cptr[idx];     // overlapped coord gather
#pragma unroll
                    for (int j = 0; j < 16; j++) if (sc[j] == m) sc[j] = 0u;
                    tmax = sc[0];
#pragma unroll
                    for (int j = 1; j < 16; j++) tmax = max(tmax, sc[j]);
                }
            }
        }
    }
    __syncthreads();    // the only block barrier

    // ---- Phase 2: warps 0 and 8 run greedy NMS for their half. ----
    if (hw == 0) {
        unsigned vp[2];
        float vx[2], vy[2];
#pragma unroll
        for (int q = 0; q < 2; q++) {
            const int s = lane + 32 * q;        // slots 48..63 are empty (0)
            vp[q] = skey[h][s];
            if (s < SURV) {
                const float2 c = scoord[h][s];
                vx[q] = c.x;  vy[q] = c.y;
            } else { vx[q] = 0.f; vy[q] = 0.f; }
        }

        float* out_prob = out + (size_t)NMS_B * NMS_K * NMS_T * 2;
        float* out_goal = out_prob + (size_t)NMS_B * NMS_K;
        float  s0 = 0.0f;   // round-0 score (fallback semantics)

#pragma unroll
        for (int r = 0; r < NMS_K; r++) {
            unsigned m = max(vp[0], vp[1]);
#pragma unroll
            for (int off = 16; off > 0; off >>= 1)
                m = max(m, __shfl_xor_sync(0xFFFFFFFFu, m, off));

            if (m == 0u) {
                // Fallback: reference keeps sel_idx = 0 -> round-0 point's
                // score/traj, goal (0,0).
                if (lane == 0) {
                    sel_i[h][r] = -1;
                    out_prob[(size_t)b * NMS_K + r]           = s0;
                    out_goal[((size_t)b * NMS_K + r) * 2 + 0] = 0.0f;
                    out_goal[((size_t)b * NMS_K + r) * 2 + 1] = 0.0f;
                    __threadfence_block();
                    flags[h][r] = 1;
                }
            } else {
                const unsigned b0 = __ballot_sync(0xFFFFFFFFu, vp[0] == m);
                const unsigned b1 = __ballot_sync(0xFFFFFFFFu, vp[1] == m);
                int qsel, wl;
                if (b0) { qsel = 0; wl = __ffs(b0) - 1; }
                else    { qsel = 1; wl = __ffs(b1) - 1; }

                const float fx = (qsel == 0) ? vx[0] : vx[1];
                const float fy = (qsel == 0) ? vy[0] : vy[1];
                const float px = __shfl_sync(0xFFFFFFFFu, fx, wl);
                const float py = __shfl_sync(0xFFFFFFFFu, fy, wl);
                if (r == 0) s0 = __uint_as_float(m);

                if (lane == 0) {
                    sel_i[h][r] = sidx[h][wl + 32 * qsel];
                    out_prob[(size_t)b * NMS_K + r]           = __uint_as_float(m);
                    out_goal[((size_t)b * NMS_K + r) * 2 + 0] = px;
                    out_goal[((size_t)b * NMS_K + r) * 2 + 1] = py;
                    __threadfence_block();
                    flags[h][r] = 1;    // release this round's selection
                }
                // Suppress survivors within thr (incl. the winner itself).
#pragma unroll
                for (int q = 0; q < 2; q++) {
                    const float dx = vx[q] - px;
                    const float dy = vy[q] - py;
                    if (dx * dx + dy * dy < NMS_THR2) vp[q] = 0u;
                }
            }
            __syncwarp();
        }
    }
    // ---- Phase 3: traj gathers start as soon as their round resolves. ----
    else if (hw <= NMS_K) {             // warps 1..6 / 9..14 -> row (hw-1)
        const int r = hw - 1;
        while (flags[h][r] == 0) { }
        __threadfence_block();
        const int sr = sel_i[h][r];
        int src = (sr >= 0) ? sr : sel_i[h][0];
        if (src < 0) src = 0;           // unreachable; memory safety only
        if (lane < 15) {
            ((float4*)out)[((size_t)b * NMS_K + r) * 15 + lane] =
                ((const float4*)traj)[((size_t)b * NMS_N + src) * 15 + lane];
        }
    }
    // warps 7 and 15: done after phase 1.
}

extern "C" void kernel_launch(void* const* d_in, const int* in_sizes, int n_in,
                              void* d_out, int out_size) {
    const float* coord = (const float*)d_in[0];  // outputs_coord     [B,1,N,2]
    const float* cls   = (const float*)d_in[1];  // outputs_class     [B,1,N]
    const float* traj  = (const float*)d_in[2];  // outputs_traj      [B,1,N,T,2]
    const float* cent  = (const float*)d_in[3];  // outputs_centerness[B,1,N]
    float* out = (float*)d_out;

    nms_goals_kernel<<<NMS_B / 2, THREADS>>>(coord, cls, traj, cent, out);
}